// round 17
// baseline (speedup 1.0000x reference)
#include <cuda_runtime.h>
#include <cuda_fp16.h>
#include <cstddef>

#define HW   4096
#define CIN  256
#define CHD  128
#define BB   4
#define MT   128   // query tile per CTA
#define NT   64    // key tile per iteration

// Scratch (allocation-free device globals) — fp16 storage
__device__ __half g_Q[BB * HW * CHD];   // [b][m][c]
__device__ __half g_K[BB * HW * CHD];   // [b][n][c]
__device__ __half g_V[BB * CIN * HW];   // [b][cv][n]

__device__ __forceinline__ void mma_f16(float c[4],
                                        unsigned a0, unsigned a1, unsigned a2, unsigned a3,
                                        unsigned b0, unsigned b1) {
    asm volatile(
        "mma.sync.aligned.m16n8k16.row.col.f32.f16.f16.f32 "
        "{%0,%1,%2,%3}, {%4,%5,%6,%7}, {%8,%9}, {%0,%1,%2,%3};\n"
        : "+f"(c[0]), "+f"(c[1]), "+f"(c[2]), "+f"(c[3])
        : "r"(a0), "r"(a1), "r"(a2), "r"(a3), "r"(b0), "r"(b1));
}

__device__ __forceinline__ void ldsm_x4(unsigned& r0, unsigned& r1, unsigned& r2, unsigned& r3,
                                        unsigned addr) {
    asm volatile("ldmatrix.sync.aligned.m8n8.x4.shared.b16 {%0,%1,%2,%3}, [%4];"
                 : "=r"(r0), "=r"(r1), "=r"(r2), "=r"(r3) : "r"(addr));
}
__device__ __forceinline__ void ldsm_x4_t(unsigned& r0, unsigned& r1, unsigned& r2, unsigned& r3,
                                          unsigned addr) {
    asm volatile("ldmatrix.sync.aligned.m8n8.x4.trans.shared.b16 {%0,%1,%2,%3}, [%4];"
                 : "=r"(r0), "=r"(r1), "=r"(r2), "=r"(r3) : "r"(addr));
}

__device__ __forceinline__ void cp_async16(unsigned dst_smem, const void* src) {
    asm volatile("cp.async.cg.shared.global [%0], [%1], 16;\n"
                 :: "r"(dst_smem), "l"(src));
}
__device__ __forceinline__ void cp_async_commit() {
    asm volatile("cp.async.commit_group;\n");
}
__device__ __forceinline__ void cp_async_wait1() {
    asm volatile("cp.async.wait_group 1;\n");
}

// ---------------------------------------------------------------------------
// Tensor-core fp16 projections.  CTA tile: 64 (o) x 128 (pos), K=256 resident.
// smem: Wt [64][264] fp16 (33.8KB) + Xt [256][136] fp16 (69.6KB) = 103.4KB.
// 8 warps.  proj_v16: warps 2(o) x 4(n).  proj_t16: warps 4(pos) x 2(o).
// ---------------------------------------------------------------------------
#define WT_STR 264   // 256 + 8 halfs pad
#define XT_STR 136   // 128 + 8 halfs pad

// V-style output: Out[b][o][n]  (o rows, pos contiguous)
__global__ __launch_bounds__(256, 2)
void proj_v16(const float* __restrict__ W, const float* __restrict__ bias,
              const float* __restrict__ X, __half* __restrict__ Out, int O) {
    extern __shared__ __half sp[];
    __half* Wt = sp;                    // [64][WT_STR]
    __half* Xt = Wt + 64 * WT_STR;      // [256][XT_STR]

    const int tid  = threadIdx.x;
    const int n0   = blockIdx.x * 128;
    const int o0   = blockIdx.y * 64;
    const int b    = blockIdx.z;
    const int w    = tid >> 5;
    const int lane = tid & 31;
    const int g    = lane >> 2;
    const int t    = lane & 3;
    const int wo   = w >> 2;     // o half (0-1)
    const int wn   = w & 3;      // n quarter (0-3)
    const float* Xb = X + (size_t)b * CIN * HW;

    // fill Wt (fp32 -> fp16)
    for (int idx = tid; idx < 64 * 64; idx += 256) {
        int r = idx >> 6, c4 = (idx & 63) << 2;
        float4 v = *(const float4*)&W[(size_t)(o0 + r) * CIN + c4];
        __half2 h[2] = { __floats2half2_rn(v.x, v.y), __floats2half2_rn(v.z, v.w) };
        *(uint2*)&Wt[r * WT_STR + c4] = *(uint2*)h;
    }
    // fill Xt (fp32 -> fp16), layout [c][n]
    for (int idx = tid; idx < 256 * 32; idx += 256) {
        int r = idx >> 5, c4 = (idx & 31) << 2;
        float4 v = *(const float4*)&Xb[(size_t)r * HW + n0 + c4];
        __half2 h[2] = { __floats2half2_rn(v.x, v.y), __floats2half2_rn(v.z, v.w) };
        *(uint2*)&Xt[r * XT_STR + c4] = *(uint2*)h;
    }
    __syncthreads();

    const unsigned wtB = (unsigned)__cvta_generic_to_shared(Wt);
    const unsigned xtB = (unsigned)__cvta_generic_to_shared(Xt);

    // A (W, row-major [o][k]) non-trans x4
    const int a_off = (wo * 32 + (lane & 15)) * WT_STR + ((lane >> 4) << 3);
    // B (X, [k][n]) trans x4: two n8 blocks
    const int bkrow = (lane & 7) + (((lane >> 3) & 1) << 3);
    const int b_off = bkrow * XT_STR + wn * 32 + ((lane >> 4) << 3);

    float acc[2][4][4] = {};
    #pragma unroll
    for (int ks = 0; ks < 16; ks++) {
        int kc = ks * 16;
        unsigned a[2][4];
        ldsm_x4(a[0][0], a[0][1], a[0][2], a[0][3], wtB + (unsigned)(a_off + kc) * 2u);
        ldsm_x4(a[1][0], a[1][1], a[1][2], a[1][3], wtB + (unsigned)(a_off + 16 * WT_STR + kc) * 2u);
        #pragma unroll
        for (int nfp = 0; nfp < 2; nfp++) {
            unsigned b0, b1, b2, b3;
            ldsm_x4_t(b0, b1, b2, b3, xtB + (unsigned)(b_off + kc * XT_STR + nfp * 16) * 2u);
            mma_f16(acc[0][2 * nfp],     a[0][0], a[0][1], a[0][2], a[0][3], b0, b1);
            mma_f16(acc[1][2 * nfp],     a[1][0], a[1][1], a[1][2], a[1][3], b0, b1);
            mma_f16(acc[0][2 * nfp + 1], a[0][0], a[0][1], a[0][2], a[0][3], b2, b3);
            mma_f16(acc[1][2 * nfp + 1], a[1][0], a[1][1], a[1][2], a[1][3], b2, b3);
        }
    }

    #pragma unroll
    for (int mf = 0; mf < 2; mf++) {
        int o_g = o0 + wo * 32 + mf * 16 + g;
        float bi0 = bias[o_g], bi1 = bias[o_g + 8];
        #pragma unroll
        for (int nf = 0; nf < 4; nf++) {
            int n = n0 + wn * 32 + nf * 8 + 2 * t;
            *(__half2*)&Out[((size_t)b * O + o_g) * HW + n] =
                __floats2half2_rn(acc[mf][nf][0] + bi0, acc[mf][nf][1] + bi0);
            *(__half2*)&Out[((size_t)b * O + o_g + 8) * HW + n] =
                __floats2half2_rn(acc[mf][nf][2] + bi1, acc[mf][nf][3] + bi1);
        }
    }
}

// Transposed output: Out[b][n][O]  (pos rows, o contiguous) — for Q/K
__global__ __launch_bounds__(256, 2)
void proj_t16(const float* __restrict__ W, const float* __restrict__ bias,
              const float* __restrict__ X, __half* __restrict__ Out, int O) {
    extern __shared__ __half sp[];
    __half* Wt = sp;                    // [64][WT_STR]
    __half* Xt = Wt + 64 * WT_STR;      // [256][XT_STR]

    const int tid  = threadIdx.x;
    const int n0   = blockIdx.x * 128;  // pos tile (M dim)
    const int o0   = blockIdx.y * 64;   // o tile (N dim)
    const int b    = blockIdx.z;
    const int w    = tid >> 5;
    const int lane = tid & 31;
    const int g    = lane >> 2;
    const int t    = lane & 3;
    const int wm   = w & 3;      // pos quarter (0-3)
    const int wo   = w >> 2;     // o half (0-1)
    const float* Xb = X + (size_t)b * CIN * HW;

    for (int idx = tid; idx < 64 * 64; idx += 256) {
        int r = idx >> 6, c4 = (idx & 63) << 2;
        float4 v = *(const float4*)&W[(size_t)(o0 + r) * CIN + c4];
        __half2 h[2] = { __floats2half2_rn(v.x, v.y), __floats2half2_rn(v.z, v.w) };
        *(uint2*)&Wt[r * WT_STR + c4] = *(uint2*)h;
    }
    for (int idx = tid; idx < 256 * 32; idx += 256) {
        int r = idx >> 5, c4 = (idx & 31) << 2;
        float4 v = *(const float4*)&Xb[(size_t)r * HW + n0 + c4];
        __half2 h[2] = { __floats2half2_rn(v.x, v.y), __floats2half2_rn(v.z, v.w) };
        *(uint2*)&Xt[r * XT_STR + c4] = *(uint2*)h;
    }
    __syncthreads();

    const unsigned wtB = (unsigned)__cvta_generic_to_shared(Wt);
    const unsigned xtB = (unsigned)__cvta_generic_to_shared(Xt);

    // A (X^T: positions as m) from Xt [k][n] via trans x4
    const int akrow = (lane & 7) + ((lane >> 4) << 3);
    const int a_off = akrow * XT_STR + wm * 32 + (((lane >> 3) & 1) << 3);
    // B (W^T: o as n) from Wt [o][k] non-trans x4
    const int brow4 = (lane & 7) + ((lane >> 4) << 3);
    const int b_off = (wo * 32 + brow4) * WT_STR + (((lane >> 3) & 1) << 3);

    float acc[2][4][4] = {};
    #pragma unroll
    for (int ks = 0; ks < 16; ks++) {
        int kc = ks * 16;
        unsigned a[2][4];
        ldsm_x4_t(a[0][0], a[0][1], a[0][2], a[0][3], xtB + (unsigned)(a_off + kc * XT_STR) * 2u);
        ldsm_x4_t(a[1][0], a[1][1], a[1][2], a[1][3], xtB + (unsigned)(a_off + kc * XT_STR + 16) * 2u);
        #pragma unroll
        for (int nfp = 0; nfp < 2; nfp++) {
            unsigned b0, b1, b2, b3;
            ldsm_x4(b0, b1, b2, b3, wtB + (unsigned)(b_off + nfp * 16 * WT_STR + kc) * 2u);
            mma_f16(acc[0][2 * nfp],     a[0][0], a[0][1], a[0][2], a[0][3], b0, b1);
            mma_f16(acc[1][2 * nfp],     a[1][0], a[1][1], a[1][2], a[1][3], b0, b1);
            mma_f16(acc[0][2 * nfp + 1], a[0][0], a[0][1], a[0][2], a[0][3], b2, b3);
            mma_f16(acc[1][2 * nfp + 1], a[1][0], a[1][1], a[1][2], a[1][3], b2, b3);
        }
    }

    #pragma unroll
    for (int mf = 0; mf < 2; mf++) {
        int mrow = n0 + wm * 32 + mf * 16 + g;
        #pragma unroll
        for (int nf = 0; nf < 4; nf++) {
            int oc = o0 + wo * 32 + nf * 8 + 2 * t;
            float2 bb = *(const float2*)&bias[oc];
            *(__half2*)&Out[((size_t)b * HW + mrow) * O + oc] =
                __floats2half2_rn(acc[mf][nf][0] + bb.x, acc[mf][nf][1] + bb.y);
            *(__half2*)&Out[((size_t)b * HW + mrow + 8) * O + oc] =
                __floats2half2_rn(acc[mf][nf][2] + bb.x, acc[mf][nf][3] + bb.y);
        }
    }
}

// ---------------------------------------------------------------------------
// Flash attention, fp16 mma.sync m16n8k16 + ldmatrix(x4) + cp.async. 256 thr.
// grid (HW/128, B) = 128 CTAs (1 wave), ~107KB smem.
// ---------------------------------------------------------------------------
#define QS_STR 136   // 128 + 8 halfs pad (16B)  -> conflict-free ldmatrix
#define VS_STR 72    // 64 + 8 halfs pad

__global__ __launch_bounds__(256)
void attn_kernel(const float* __restrict__ resid, float* __restrict__ out) {
    extern __shared__ __half smh[];
    __half* Qs  = smh;                  // [128][136]
    __half* Ks  = Qs + 128 * QS_STR;    // [64][136]
    __half* Vs  = Ks + 64 * QS_STR;     // [256][72]
    __half* Ps  = Vs + 256 * VS_STR;    // [128][72]
    float* pmax = (float*)(Ps + 128 * VS_STR);  // [2][128]
    float* psum = pmax + 256;                   // [2][128]

    const int tid  = threadIdx.x;
    const int b    = blockIdx.y;
    const int m0g  = blockIdx.x * MT;
    const int w    = tid >> 5;
    const int lane = tid & 31;
    const int g    = lane >> 2;
    const int t    = lane & 3;
    const int wm   = w & 3;        // m-quarter
    const int wh   = w >> 2;       // n-half (S) / cv-half (O)
    const int m0w  = wm * 32;
    const int n0w  = wh * 32;
    const int cv0w = wh * 128;

    const __half* Q = g_Q + (size_t)b * HW * CHD;
    const __half* K = g_K + (size_t)b * HW * CHD;
    const __half* V = g_V + (size_t)b * CIN * HW;

    const unsigned qsB = (unsigned)__cvta_generic_to_shared(Qs);
    const unsigned ksB = (unsigned)__cvta_generic_to_shared(Ks);
    const unsigned vsB = (unsigned)__cvta_generic_to_shared(Vs);
    const unsigned psB = (unsigned)__cvta_generic_to_shared(Ps);

    const int l15   = lane & 15;
    const int asel  = (lane >> 4) << 3;
    const int brow4 = (lane & 7) + ((lane >> 4) << 3);
    const int bsel4 = ((lane >> 3) & 1) << 3;
    const int a_q  = (m0w + l15) * QS_STR + asel;
    const int b_k4 = (n0w + brow4) * QS_STR + bsel4;
    const int a_p  = (m0w + l15) * VS_STR + asel;
    const int b_v4 = (cv0w + brow4) * VS_STR + bsel4;

    for (int idx = tid; idx < 128 * 16; idx += 256) {
        int r = idx >> 4, c8 = (idx & 15) << 3;
        cp_async16(qsB + (unsigned)(r * QS_STR + c8) * 2u, &Q[(size_t)(m0g + r) * CHD + c8]);
    }
    for (int idx = tid; idx < 64 * 16; idx += 256) {
        int r = idx >> 4, c8 = (idx & 15) << 3;
        cp_async16(ksB + (unsigned)(r * QS_STR + c8) * 2u, &K[(size_t)r * CHD + c8]);
    }
    cp_async_commit();

    float rowM[2][2], rowL[2][2], alpha[2][2];
    #pragma unroll
    for (int mf = 0; mf < 2; mf++) {
        rowM[mf][0] = -1e30f; rowM[mf][1] = -1e30f;
        rowL[mf][0] = 0.0f;   rowL[mf][1] = 0.0f;
    }

    float oacc[2][16][4];
    #pragma unroll
    for (int mf = 0; mf < 2; mf++)
        #pragma unroll
        for (int cf = 0; cf < 16; cf++)
            #pragma unroll
            for (int e = 0; e < 4; e++) oacc[mf][cf][e] = 0.0f;

    for (int nt = 0; nt < HW; nt += NT) {
        __syncthreads();

        for (int idx = tid; idx < 256 * 8; idx += 256) {
            int r = idx >> 3, c8 = (idx & 7) << 3;
            cp_async16(vsB + (unsigned)(r * VS_STR + c8) * 2u, &V[(size_t)r * HW + nt + c8]);
        }
        cp_async_commit();

        cp_async_wait1();
        __syncthreads();

        // ---- S = Q Kt ----
        float sacc[2][4][4] = {};
        #pragma unroll
        for (int ks = 0; ks < 8; ks++) {
            int kc = ks * 16;
            unsigned a[2][4];
            ldsm_x4(a[0][0], a[0][1], a[0][2], a[0][3], qsB + (unsigned)(a_q + kc) * 2u);
            ldsm_x4(a[1][0], a[1][1], a[1][2], a[1][3], qsB + (unsigned)(a_q + 16 * QS_STR + kc) * 2u);
            #pragma unroll
            for (int nfp = 0; nfp < 2; nfp++) {
                unsigned b0, b1, b2, b3;
                ldsm_x4(b0, b1, b2, b3, ksB + (unsigned)(b_k4 + nfp * 16 * QS_STR + kc) * 2u);
                mma_f16(sacc[0][2 * nfp],     a[0][0], a[0][1], a[0][2], a[0][3], b0, b1);
                mma_f16(sacc[1][2 * nfp],     a[1][0], a[1][1], a[1][2], a[1][3], b0, b1);
                mma_f16(sacc[0][2 * nfp + 1], a[0][0], a[0][1], a[0][2], a[0][3], b2, b3);
                mma_f16(sacc[1][2 * nfp + 1], a[1][0], a[1][1], a[1][2], a[1][3], b2, b3);
            }
        }

        float lm[2][2];
        #pragma unroll
        for (int mf = 0; mf < 2; mf++) {
            float lm0 = -1e30f, lm1 = -1e30f;
            #pragma unroll
            for (int nf = 0; nf < 4; nf++) {
                lm0 = fmaxf(lm0, fmaxf(sacc[mf][nf][0], sacc[mf][nf][1]));
                lm1 = fmaxf(lm1, fmaxf(sacc[mf][nf][2], sacc[mf][nf][3]));
            }
            lm0 = fmaxf(lm0, __shfl_xor_sync(0xffffffffu, lm0, 1));
            lm0 = fmaxf(lm0, __shfl_xor_sync(0xffffffffu, lm0, 2));
            lm1 = fmaxf(lm1, __shfl_xor_sync(0xffffffffu, lm1, 1));
            lm1 = fmaxf(lm1, __shfl_xor_sync(0xffffffffu, lm1, 2));
            lm[mf][0] = lm0; lm[mf][1] = lm1;
            if (t == 0) {
                pmax[wh * 128 + m0w + mf * 16 + g]     = lm0;
                pmax[wh * 128 + m0w + mf * 16 + g + 8] = lm1;
            }
        }
        __syncthreads();

        {
            int ntn = (nt + NT < HW) ? nt + NT : 0;
            for (int idx = tid; idx < 64 * 16; idx += 256) {
                int r = idx >> 4, c8 = (idx & 15) << 3;
                cp_async16(ksB + (unsigned)(r * QS_STR + c8) * 2u,
                           &K[(size_t)(ntn + r) * CHD + c8]);
            }
            cp_async_commit();
        }

        const float* pmaxO = pmax + (wh ^ 1) * 128;
        #pragma unroll
        for (int mf = 0; mf < 2; mf++) {
            int r0 = m0w + mf * 16 + g;
            float nm0 = fmaxf(rowM[mf][0], fmaxf(lm[mf][0], pmaxO[r0]));
            float nm1 = fmaxf(rowM[mf][1], fmaxf(lm[mf][1], pmaxO[r0 + 8]));
            alpha[mf][0] = __expf(rowM[mf][0] - nm0);
            alpha[mf][1] = __expf(rowM[mf][1] - nm1);
            rowM[mf][0] = nm0; rowM[mf][1] = nm1;
        }

        float ls[2][2];
        #pragma unroll
        for (int mf = 0; mf < 2; mf++) {
            int r0 = m0w + mf * 16 + g;
            float nm0 = rowM[mf][0], nm1 = rowM[mf][1];
            float ls0 = 0.0f, ls1 = 0.0f;
            #pragma unroll
            for (int nf = 0; nf < 4; nf++) {
                __half2 ph01 = __floats2half2_rn(__expf(sacc[mf][nf][0] - nm0),
                                                 __expf(sacc[mf][nf][1] - nm0));
                __half2 ph23 = __floats2half2_rn(__expf(sacc[mf][nf][2] - nm1),
                                                 __expf(sacc[mf][nf][3] - nm1));
                float2 pf01 = __half22float2(ph01);
                float2 pf23 = __half22float2(ph23);
                ls0 += pf01.x + pf01.y;
                ls1 += pf23.x + pf23.y;
                int n = n0w + nf * 8 + 2 * t;
                *(__half2*)&Ps[r0 * VS_STR + n]       = ph01;
                *(__half2*)&Ps[(r0 + 8) * VS_STR + n] = ph23;
            }
            ls0 += __shfl_xor_sync(0xffffffffu, ls0, 1);
            ls0 += __shfl_xor_sync(0xffffffffu, ls0, 2);
            ls1 += __shfl_xor_sync(0xffffffffu, ls1, 1);
            ls1 += __shfl_xor_sync(0xffffffffu, ls1, 2);
            ls[mf][0] = ls0; ls[mf][1] = ls1;
            if (t == 0) {
                psum[wh * 128 + r0]     = ls0;
                psum[wh * 128 + r0 + 8] = ls1;
            }
        }
        cp_async_wait1();
        __syncthreads();

        const float* psumO = psum + (wh ^ 1) * 128;
        #pragma unroll
        for (int mf = 0; mf < 2; mf++) {
            int r0 = m0w + mf * 16 + g;
            rowL[mf][0] = rowL[mf][0] * alpha[mf][0] + ls[mf][0] + psumO[r0];
            rowL[mf][1] = rowL[mf][1] * alpha[mf][1] + ls[mf][1] + psumO[r0 + 8];
        }

        #pragma unroll
        for (int mf = 0; mf < 2; mf++) {
            float al0 = alpha[mf][0];
            float al1 = alpha[mf][1];
            #pragma unroll
            for (int cf = 0; cf < 16; cf++) {
                oacc[mf][cf][0] *= al0; oacc[mf][cf][1] *= al0;
                oacc[mf][cf][2] *= al1; oacc[mf][cf][3] *= al1;
            }
        }
        #pragma unroll
        for (int kn = 0; kn < 4; kn++) {
            int kc = kn * 16;
            unsigned a[2][4];
            ldsm_x4(a[0][0], a[0][1], a[0][2], a[0][3], psB + (unsigned)(a_p + kc) * 2u);
            ldsm_x4(a[1][0], a[1][1], a[1][2], a[1][3], psB + (unsigned)(a_p + 16 * VS_STR + kc) * 2u);
            #pragma unroll
            for (int cfp = 0; cfp < 8; cfp++) {
                unsigned b0, b1, b2, b3;
                ldsm_x4(b0, b1, b2, b3, vsB + (unsigned)(b_v4 + cfp * 16 * VS_STR + kc) * 2u);
                mma_f16(oacc[0][2 * cfp],     a[0][0], a[0][1], a[0][2], a[0][3], b0, b1);
                mma_f16(oacc[1][2 * cfp],     a[1][0], a[1][1], a[1][2], a[1][3], b0, b1);
                mma_f16(oacc[0][2 * cfp + 1], a[0][0], a[0][1], a[0][2], a[0][3], b2, b3);
                mma_f16(oacc[1][2 * cfp + 1], a[1][0], a[1][1], a[1][2], a[1][3], b2, b3);
            }
        }
    }

    // ---- epilogue ----
    #pragma unroll
    for (int mf = 0; mf < 2; mf++) {
        int r0 = m0w + mf * 16 + g;
        float il0 = 1.0f / rowL[mf][0];
        float il1 = 1.0f / rowL[mf][1];
        int mg = m0g + r0;
        #pragma unroll
        for (int cf = 0; cf < 16; cf++) {
            int cv = cv0w + cf * 8 + 2 * t;
            size_t i0 = ((size_t)(b * CIN + cv)) * HW + mg;
            size_t i1 = i0 + HW;
            out[i0]     = oacc[mf][cf][0] * il0 + resid[i0];
            out[i1]     = oacc[mf][cf][1] * il0 + resid[i1];
            out[i0 + 8] = oacc[mf][cf][2] * il1 + resid[i0 + 8];
            out[i1 + 8] = oacc[mf][cf][3] * il1 + resid[i1 + 8];
        }
    }
}

// ---------------------------------------------------------------------------
extern "C" void kernel_launch(void* const* d_in, const int* in_sizes, int n_in,
                              void* d_out, int out_size) {
    const float* a  = (const float*)d_in[0];
    const float* p  = (const float*)d_in[1];
    const float* Wq = (const float*)d_in[2];
    const float* bq = (const float*)d_in[3];
    const float* Wk = (const float*)d_in[4];
    const float* bk = (const float*)d_in[5];
    const float* Wv = (const float*)d_in[6];
    const float* bv = (const float*)d_in[7];
    float* out = (float*)d_out;

    __half *dQ, *dK, *dV;
    cudaGetSymbolAddress((void**)&dQ, g_Q);
    cudaGetSymbolAddress((void**)&dK, g_K);
    cudaGetSymbolAddress((void**)&dV, g_V);

    const int psmem = (64 * WT_STR + 256 * XT_STR) * 2;   // 103424
    cudaFuncSetAttribute(proj_t16, cudaFuncAttributeMaxDynamicSharedMemorySize, psmem);
    cudaFuncSetAttribute(proj_v16, cudaFuncAttributeMaxDynamicSharedMemorySize, psmem);

    dim3 blk(256);
    proj_t16<<<dim3(HW / 128, CHD / 64, BB), blk, psmem>>>(Wq, bq, a, dQ, CHD);
    proj_t16<<<dim3(HW / 128, CHD / 64, BB), blk, psmem>>>(Wk, bk, p, dK, CHD);
    proj_v16<<<dim3(HW / 128, CIN / 64, BB), blk, psmem>>>(Wv, bv, p, dV, CIN);

    const int smem = (128 * QS_STR + 64 * QS_STR + 256 * VS_STR + 128 * VS_STR) * 2 + 512 * 4;
    cudaFuncSetAttribute(attn_kernel, cudaFuncAttributeMaxDynamicSharedMemorySize, smem);
    attn_kernel<<<dim3(HW / MT, BB), blk, smem>>>(a, out);
}